// round 17
// baseline (speedup 1.0000x reference)
#include <cuda_runtime.h>
#include <cuda_fp16.h>

// ---------------- problem constants ----------------
#define NMAX 100000
#define GMAX 2048
#define EMAXT 3301024   // E + N + margin

// ---------------- scratch ----------------
__device__ __align__(16) __half g_h1h[NMAX * 64];     // h1 in fp16
__device__ __align__(16) float  g_als1[NMAX * 4];
__device__ __align__(16) float  g_ald1[NMAX * 4];
__device__ __align__(16) __half g_x2h[NMAX * 64];     // x2 in fp16
__device__ __align__(16) float  g_als2[NMAX * 4];
__device__ __align__(16) float  g_ald2[NMAX * 4];
__device__ __align__(16) __half g_haggh[NMAX * 256];  // [n][head][64] fp16
__device__ __align__(16) float  g_ws2[256];
__device__ __align__(16) float  g_wd2[256];
__device__ __align__(16) float  g_sums[GMAX * 128];
__device__ __align__(16) float  g_cnt[GMAX];
// CSR
__device__ int g_deg[NMAX];
__device__ int g_rs[NMAX + 1];
__device__ int g_cur[NMAX];
__device__ int g_esrc[EMAXT];
__device__ int g_bs[512];

// ---------------- helpers ----------------
__device__ __forceinline__ float lrelu(float e) { return e > 0.f ? e : 0.2f * e; }
__device__ __forceinline__ void red4(float* p, float a, float b, float c, float d) {
    asm volatile("red.global.add.v4.f32 [%0], {%1,%2,%3,%4};"
                 :: "l"(p), "f"(a), "f"(b), "f"(c), "f"(d) : "memory");
}

// ---------------- CSR build ----------------
__global__ void k_deg(const int* __restrict__ ei, int E) {
    int t = blockIdx.x * blockDim.x + threadIdx.x;
    if (t >= E) return;
    atomicAdd(&g_deg[ei[(size_t)E + t]], 1);
}

__global__ void k_s1(int N) {
    __shared__ int sh[256];
    int t = threadIdx.x;
    int i = blockIdx.x * 256 + t;
    int v = (i < N) ? g_deg[i] + 1 : 0;   // +1 self loop
    sh[t] = v;
    __syncthreads();
    for (int o = 1; o < 256; o <<= 1) {
        int add = (t >= o) ? sh[t - o] : 0;
        __syncthreads();
        sh[t] += add;
        __syncthreads();
    }
    if (i < N) g_rs[i] = sh[t] - v;
    if (t == 255) g_bs[blockIdx.x] = sh[255];
}

__global__ void k_s2(int nb) {
    __shared__ int sh[512];
    int t = threadIdx.x;
    int v = (t < nb) ? g_bs[t] : 0;
    sh[t] = v;
    __syncthreads();
    for (int o = 1; o < 512; o <<= 1) {
        int add = (t >= o) ? sh[t - o] : 0;
        __syncthreads();
        sh[t] += add;
        __syncthreads();
    }
    if (t < nb) g_bs[t] = sh[t] - v;
}

__global__ void k_s3(int N, int T) {
    int i = blockIdx.x * 256 + threadIdx.x;
    if (i < N) {
        int v = g_rs[i] + g_bs[blockIdx.x];
        g_rs[i] = v;
        g_cur[i] = v;
    }
    if (i == N) g_rs[N] = T;
}

__global__ void k_fill(const int* __restrict__ ei, int E, int N) {
    int t = blockIdx.x * blockDim.x + threadIdx.x;
    if (t >= E + N) return;
    int s, d;
    if (t < E) { s = ei[t]; d = ei[(size_t)E + t]; }
    else       { s = d = t - E; }
    int pos = atomicAdd(&g_cur[d], 1);
    g_esrc[pos] = s;
}

// ---------------- GEMM 1 (register-tiled 4x4) + fused attention logits --------
__global__ void k_gemm1(const float* __restrict__ x, const float* __restrict__ W,
                        const float* __restrict__ a_s, const float* __restrict__ a_d, int N) {
    __shared__ float sW[128 * 64];
    __shared__ float sx[32][68];
    int tid = threadIdx.x;
    for (int i = tid; i < 128 * 16; i += 256)
        *(float4*)&sW[i * 4] = __ldg(&((const float4*)W)[i]);
    int tr = tid >> 4;
    int tc = tid & 15;
    int rowBase = blockIdx.x * 64;
    float acc[4][4] = {};
    int lr = tid >> 2;
    int lk = tid & 3;
    for (int kc = 0; kc < 4; kc++) {
        __syncthreads();
#pragma unroll
        for (int half_ = 0; half_ < 2; half_++) {
            int kl = half_ * 16 + lk * 4;
            int grow = rowBase + lr;
            float4 v = make_float4(0.f, 0.f, 0.f, 0.f);
            if (grow < N) v = __ldg((const float4*)(x + (size_t)grow * 128 + kc * 32 + kl));
            sx[kl + 0][lr] = v.x;
            sx[kl + 1][lr] = v.y;
            sx[kl + 2][lr] = v.z;
            sx[kl + 3][lr] = v.w;
        }
        __syncthreads();
#pragma unroll
        for (int kl = 0; kl < 32; kl++) {
            int k = kc * 32 + kl;
            float4 xv = *(const float4*)&sx[kl][tr * 4];
            float4 wv = *(const float4*)&sW[k * 64 + tc * 4];
            acc[0][0] = fmaf(xv.x, wv.x, acc[0][0]); acc[0][1] = fmaf(xv.x, wv.y, acc[0][1]);
            acc[0][2] = fmaf(xv.x, wv.z, acc[0][2]); acc[0][3] = fmaf(xv.x, wv.w, acc[0][3]);
            acc[1][0] = fmaf(xv.y, wv.x, acc[1][0]); acc[1][1] = fmaf(xv.y, wv.y, acc[1][1]);
            acc[1][2] = fmaf(xv.y, wv.z, acc[1][2]); acc[1][3] = fmaf(xv.y, wv.w, acc[1][3]);
            acc[2][0] = fmaf(xv.z, wv.x, acc[2][0]); acc[2][1] = fmaf(xv.z, wv.y, acc[2][1]);
            acc[2][2] = fmaf(xv.z, wv.z, acc[2][2]); acc[2][3] = fmaf(xv.z, wv.w, acc[2][3]);
            acc[3][0] = fmaf(xv.w, wv.x, acc[3][0]); acc[3][1] = fmaf(xv.w, wv.y, acc[3][1]);
            acc[3][2] = fmaf(xv.w, wv.z, acc[3][2]); acc[3][3] = fmaf(xv.w, wv.w, acc[3][3]);
        }
    }
#pragma unroll
    for (int r = 0; r < 4; r++) {
        int row = rowBase + tr * 4 + r;
        if (row < N) {
            __half2 p[2];
            p[0] = __floats2half2_rn(acc[r][0], acc[r][1]);
            p[1] = __floats2half2_rn(acc[r][2], acc[r][3]);
            *(uint2*)(g_h1h + (size_t)row * 64 + tc * 4) = *(uint2*)p;
        }
    }
    const float4 as4 = __ldg((const float4*)(a_s + tc * 4));
    const float4 ad4 = __ldg((const float4*)(a_d + tc * 4));
    float s[4], d[4];
#pragma unroll
    for (int r = 0; r < 4; r++) {
        s[r] = acc[r][0] * as4.x + acc[r][1] * as4.y + acc[r][2] * as4.z + acc[r][3] * as4.w;
        d[r] = acc[r][0] * ad4.x + acc[r][1] * ad4.y + acc[r][2] * ad4.z + acc[r][3] * ad4.w;
    }
#pragma unroll
    for (int r = 0; r < 4; r++) {
        s[r] += __shfl_xor_sync(0xffffffffu, s[r], 1);
        d[r] += __shfl_xor_sync(0xffffffffu, d[r], 1);
        s[r] += __shfl_xor_sync(0xffffffffu, s[r], 2);
        d[r] += __shfl_xor_sync(0xffffffffu, d[r], 2);
    }
    if ((tc & 3) == 0) {
        int head = tc >> 2;
#pragma unroll
        for (int r = 0; r < 4; r++) {
            int row = rowBase + tr * 4 + r;
            if (row < N) {
                g_als1[(size_t)row * 4 + head] = s[r];
                g_ald1[(size_t)row * 4 + head] = d[r];
            }
        }
    }
}

// ---------------- layer-2 folded attention vectors ----------------
__global__ void k_wvec(const float* __restrict__ W2,
                       const float* __restrict__ a_s2, const float* __restrict__ a_d2) {
    int t = threadIdx.x;
    int h = t >> 6, k = t & 63;
    float s = 0.f, d = 0.f;
    for (int c = 0; c < 32; c++) {
        float wv = W2[k * 128 + h * 32 + c];
        s = fmaf(wv, a_s2[h * 32 + c], s);
        d = fmaf(wv, a_d2[h * 32 + c], d);
    }
    g_ws2[t] = s;
    g_wd2[t] = d;
}

// ---------------- fused layer-1 aggregation + layer-2 logits (pipelined) -----
__global__ void k_agg1(const float* __restrict__ b1, int N) {
    __shared__ int   sh_idx[8][32];
    __shared__ float sh_ex[8][32 * 4];
    int wid = threadIdx.x >> 5;
    int w = (blockIdx.x * blockDim.x + threadIdx.x) >> 5;
    int lane = threadIdx.x & 31;
    if (w >= N) return;
    int n = w;
    int start = g_rs[n], end = g_rs[n + 1];
    float4 ad = *(const float4*)(g_ald1 + (size_t)n * 4);

    int head = lane >> 3;
    float acc0 = 0.f, acc1 = 0.f;
    float4 den = make_float4(0.f, 0.f, 0.f, 0.f);

    // prologue prefetch: chunk 0
    int s_cur = 0;
    float4 a_cur = make_float4(0.f, 0.f, 0.f, 0.f);
    {
        int i = start + lane;
        if (i < end) {
            s_cur = g_esrc[i];
            a_cur = *(const float4*)(g_als1 + (size_t)s_cur * 4);
        }
    }

    for (int base = start; base < end; base += 32) {
        int cnt = min(32, end - base);
        float4 ex = make_float4(0.f, 0.f, 0.f, 0.f);
        if (base + lane < end) {
            ex.x = __expf(lrelu(a_cur.x + ad.x));
            ex.y = __expf(lrelu(a_cur.y + ad.y));
            ex.z = __expf(lrelu(a_cur.z + ad.z));
            ex.w = __expf(lrelu(a_cur.w + ad.w));
            den.x += ex.x; den.y += ex.y; den.z += ex.z; den.w += ex.w;
        }
        sh_idx[wid][lane] = s_cur;
        *(float4*)&sh_ex[wid][lane * 4] = ex;
        __syncwarp();
        // prefetch next chunk (hidden under j-loop)
        int inext = base + 32 + lane;
        int s_nxt = 0;
        float4 a_nxt = make_float4(0.f, 0.f, 0.f, 0.f);
        if (inext < end) {
            s_nxt = g_esrc[inext];
            a_nxt = *(const float4*)(g_als1 + (size_t)s_nxt * 4);
        }
        if (cnt == 32) {
#pragma unroll 8
            for (int j = 0; j < 32; j++) {
                int   sj  = sh_idx[wid][j];
                float exm = sh_ex[wid][j * 4 + head];
                float2 hv = __half22float2(*(const __half2*)(g_h1h + (size_t)sj * 64 + lane * 2));
                acc0 = fmaf(exm, hv.x, acc0);
                acc1 = fmaf(exm, hv.y, acc1);
            }
        } else {
            for (int j = 0; j < cnt; j++) {
                int   sj  = sh_idx[wid][j];
                float exm = sh_ex[wid][j * 4 + head];
                float2 hv = __half22float2(*(const __half2*)(g_h1h + (size_t)sj * 64 + lane * 2));
                acc0 = fmaf(exm, hv.x, acc0);
                acc1 = fmaf(exm, hv.y, acc1);
            }
        }
        __syncwarp();
        s_cur = s_nxt;
        a_cur = a_nxt;
    }
#pragma unroll
    for (int o = 16; o; o >>= 1) {
        den.x += __shfl_xor_sync(0xffffffffu, den.x, o);
        den.y += __shfl_xor_sync(0xffffffffu, den.y, o);
        den.z += __shfl_xor_sync(0xffffffffu, den.z, o);
        den.w += __shfl_xor_sync(0xffffffffu, den.w, o);
    }
    float dh = (head == 0) ? den.x : ((head == 1) ? den.y : ((head == 2) ? den.z : den.w));
    float inv = 1.f / (dh + 1e-16f);
    float2 o2;
    o2.x = fmaxf(acc0 * inv + b1[lane * 2], 0.f);
    o2.y = fmaxf(acc1 * inv + b1[lane * 2 + 1], 0.f);
    *(__half2*)(g_x2h + (size_t)n * 64 + lane * 2) = __floats2half2_rn(o2.x, o2.y);

    // fused layer-2 logits from fp32 registers
#pragma unroll
    for (int h = 0; h < 4; h++) {
        float2 ws = *(const float2*)(g_ws2 + h * 64 + lane * 2);
        float2 wd = *(const float2*)(g_wd2 + h * 64 + lane * 2);
        float sv = o2.x * ws.x + o2.y * ws.y;
        float dv = o2.x * wd.x + o2.y * wd.y;
#pragma unroll
        for (int o = 16; o; o >>= 1) {
            sv += __shfl_xor_sync(0xffffffffu, sv, o);
            dv += __shfl_xor_sync(0xffffffffu, dv, o);
        }
        if (lane == 0) {
            g_als2[(size_t)n * 4 + h] = sv;
            g_ald2[(size_t)n * 4 + h] = dv;
        }
    }
}

// ---------------- layer-2 aggregation in x2-space (pipelined fp16 gather) ----
__global__ void k_agg2x(int N) {
    __shared__ int   sh_idx[8][32];
    __shared__ float sh_ex[8][32 * 4];
    int wid = threadIdx.x >> 5;
    int w = (blockIdx.x * blockDim.x + threadIdx.x) >> 5;
    int lane = threadIdx.x & 31;
    if (w >= N) return;
    int n = w;
    int start = g_rs[n], end = g_rs[n + 1];
    float4 ad = *(const float4*)(g_ald2 + (size_t)n * 4);

    float a00 = 0.f, a01 = 0.f, a10 = 0.f, a11 = 0.f;
    float a20 = 0.f, a21 = 0.f, a30 = 0.f, a31 = 0.f;
    float4 den = make_float4(0.f, 0.f, 0.f, 0.f);

    // prologue prefetch: chunk 0
    int s_cur = 0;
    float4 a_cur = make_float4(0.f, 0.f, 0.f, 0.f);
    {
        int i = start + lane;
        if (i < end) {
            s_cur = g_esrc[i];
            a_cur = *(const float4*)(g_als2 + (size_t)s_cur * 4);
        }
    }

    for (int base = start; base < end; base += 32) {
        int cnt = min(32, end - base);
        float4 ex = make_float4(0.f, 0.f, 0.f, 0.f);
        if (base + lane < end) {
            ex.x = __expf(lrelu(a_cur.x + ad.x));
            ex.y = __expf(lrelu(a_cur.y + ad.y));
            ex.z = __expf(lrelu(a_cur.z + ad.z));
            ex.w = __expf(lrelu(a_cur.w + ad.w));
            den.x += ex.x; den.y += ex.y; den.z += ex.z; den.w += ex.w;
        }
        sh_idx[wid][lane] = s_cur;
        *(float4*)&sh_ex[wid][lane * 4] = ex;
        __syncwarp();
        int inext = base + 32 + lane;
        int s_nxt = 0;
        float4 a_nxt = make_float4(0.f, 0.f, 0.f, 0.f);
        if (inext < end) {
            s_nxt = g_esrc[inext];
            a_nxt = *(const float4*)(g_als2 + (size_t)s_nxt * 4);
        }
        if (cnt == 32) {
#pragma unroll 4
            for (int j = 0; j < 32; j++) {
                int    sj = sh_idx[wid][j];
                float4 e4 = *(const float4*)&sh_ex[wid][j * 4];
                float2 xv = __half22float2(*(const __half2*)(g_x2h + (size_t)sj * 64 + lane * 2));
                a00 = fmaf(e4.x, xv.x, a00); a01 = fmaf(e4.x, xv.y, a01);
                a10 = fmaf(e4.y, xv.x, a10); a11 = fmaf(e4.y, xv.y, a11);
                a20 = fmaf(e4.z, xv.x, a20); a21 = fmaf(e4.z, xv.y, a21);
                a30 = fmaf(e4.w, xv.x, a30); a31 = fmaf(e4.w, xv.y, a31);
            }
        } else {
            for (int j = 0; j < cnt; j++) {
                int    sj = sh_idx[wid][j];
                float4 e4 = *(const float4*)&sh_ex[wid][j * 4];
                float2 xv = __half22float2(*(const __half2*)(g_x2h + (size_t)sj * 64 + lane * 2));
                a00 = fmaf(e4.x, xv.x, a00); a01 = fmaf(e4.x, xv.y, a01);
                a10 = fmaf(e4.y, xv.x, a10); a11 = fmaf(e4.y, xv.y, a11);
                a20 = fmaf(e4.z, xv.x, a20); a21 = fmaf(e4.z, xv.y, a21);
                a30 = fmaf(e4.w, xv.x, a30); a31 = fmaf(e4.w, xv.y, a31);
            }
        }
        __syncwarp();
        s_cur = s_nxt;
        a_cur = a_nxt;
    }
#pragma unroll
    for (int o = 16; o; o >>= 1) {
        den.x += __shfl_xor_sync(0xffffffffu, den.x, o);
        den.y += __shfl_xor_sync(0xffffffffu, den.y, o);
        den.z += __shfl_xor_sync(0xffffffffu, den.z, o);
        den.w += __shfl_xor_sync(0xffffffffu, den.w, o);
    }
    float i0 = 1.f / (den.x + 1e-16f);
    float i1 = 1.f / (den.y + 1e-16f);
    float i2 = 1.f / (den.z + 1e-16f);
    float i3 = 1.f / (den.w + 1e-16f);
    __half* hg = g_haggh + (size_t)n * 256;
    *(__half2*)(hg +   0 + lane * 2) = __floats2half2_rn(a00 * i0, a01 * i0);
    *(__half2*)(hg +  64 + lane * 2) = __floats2half2_rn(a10 * i1, a11 * i1);
    *(__half2*)(hg + 128 + lane * 2) = __floats2half2_rn(a20 * i2, a21 * i2);
    *(__half2*)(hg + 192 + lane * 2) = __floats2half2_rn(a30 * i3, a31 * i3);
}

// ---------------- post-agg GEMM2 (register-tiled) + bias + relu + pool -------
__global__ void k_out(const float* __restrict__ W2, const float* __restrict__ b2,
                      const int* __restrict__ batch, int N) {
    __shared__ float  sW[64 * 64];      // [k][c] for this col-half (16KB)
    __shared__ __half sA[2 * 64 * 64];  // [h][k][row rotated] (16KB)
    int tid = threadIdx.x;
    int colBase = blockIdx.y * 64;
    for (int i = tid; i < 64 * 16; i += 256) {
        int k = i >> 4, c4 = i & 15;
        *(float4*)&sW[k * 64 + c4 * 4] =
            __ldg((const float4*)(W2 + k * 128 + colBase + c4 * 4));
    }
    int rowBase = blockIdx.x * 64;
    int h0 = blockIdx.y * 2;
    {
        int lr = tid >> 2;           // row 0..63
        int lq = tid & 3;            // quarter
        int hh = lq >> 1;            // head within pair
        int k0 = (lq & 1) * 32;      // k chunk
        int rot = hh * 8 + (lq & 1) * 16;
        int dstRow = (lr + rot) & 63;
        int row = rowBase + lr;
        if (row < N) {
            const uint2* src = (const uint2*)(g_haggh + (size_t)row * 256 + (h0 + hh) * 64 + k0);
#pragma unroll
            for (int u = 0; u < 8; u++) {
                uint2 v = __ldg(&src[u]);
                __half2 p0 = *(__half2*)&v.x;
                __half2 p1 = *(__half2*)&v.y;
                int k = k0 + u * 4;
                sA[hh * 4096 + (k + 0) * 64 + dstRow] = __low2half(p0);
                sA[hh * 4096 + (k + 1) * 64 + dstRow] = __high2half(p0);
                sA[hh * 4096 + (k + 2) * 64 + dstRow] = __low2half(p1);
                sA[hh * 4096 + (k + 3) * 64 + dstRow] = __high2half(p1);
            }
        } else {
            __half z = __float2half(0.f);
#pragma unroll
            for (int u = 0; u < 8; u++) {
                int k = k0 + u * 4;
                sA[hh * 4096 + (k + 0) * 64 + dstRow] = z;
                sA[hh * 4096 + (k + 1) * 64 + dstRow] = z;
                sA[hh * 4096 + (k + 2) * 64 + dstRow] = z;
                sA[hh * 4096 + (k + 3) * 64 + dstRow] = z;
            }
        }
    }
    __syncthreads();
    int tr = tid >> 4;      // rows tr*4..+3
    int tc = tid & 15;      // cols tc*4..+3
    int head = tc >> 3;     // head within this half
    float acc[4][4] = {};
#pragma unroll
    for (int k = 0; k < 64; k++) {
        int base = (tr * 4 + head * 8 + (k >> 5) * 16) & 63;
        uint2 av = *(const uint2*)&sA[head * 4096 + k * 64 + base];
        float2 a01 = __half22float2(*(const __half2*)&av.x);
        float2 a23 = __half22float2(*(const __half2*)&av.y);
        float4 w4 = *(const float4*)&sW[k * 64 + tc * 4];
        acc[0][0] = fmaf(a01.x, w4.x, acc[0][0]); acc[0][1] = fmaf(a01.x, w4.y, acc[0][1]);
        acc[0][2] = fmaf(a01.x, w4.z, acc[0][2]); acc[0][3] = fmaf(a01.x, w4.w, acc[0][3]);
        acc[1][0] = fmaf(a01.y, w4.x, acc[1][0]); acc[1][1] = fmaf(a01.y, w4.y, acc[1][1]);
        acc[1][2] = fmaf(a01.y, w4.z, acc[1][2]); acc[1][3] = fmaf(a01.y, w4.w, acc[1][3]);
        acc[2][0] = fmaf(a23.x, w4.x, acc[2][0]); acc[2][1] = fmaf(a23.x, w4.y, acc[2][1]);
        acc[2][2] = fmaf(a23.x, w4.z, acc[2][2]); acc[2][3] = fmaf(a23.x, w4.w, acc[2][3]);
        acc[3][0] = fmaf(a23.y, w4.x, acc[3][0]); acc[3][1] = fmaf(a23.y, w4.y, acc[3][1]);
        acc[3][2] = fmaf(a23.y, w4.z, acc[3][2]); acc[3][3] = fmaf(a23.y, w4.w, acc[3][3]);
    }
    const float4 bb = __ldg((const float4*)(b2 + colBase + tc * 4));
#pragma unroll
    for (int r = 0; r < 4; r++) {
        int row = rowBase + tr * 4 + r;
        if (row < N) {
            float o0 = fmaxf(acc[r][0] + bb.x, 0.f);
            float o1 = fmaxf(acc[r][1] + bb.y, 0.f);
            float o2 = fmaxf(acc[r][2] + bb.z, 0.f);
            float o3 = fmaxf(acc[r][3] + bb.w, 0.f);
            int g = __ldg(&batch[row]);
            red4(g_sums + (size_t)g * 128 + colBase + tc * 4, o0, o1, o2, o3);
            if (tc == 0 && blockIdx.y == 0) atomicAdd(&g_cnt[g], 1.f);
        }
    }
}

// ---------------- pool divide ----------------
__global__ void k_pool(float* __restrict__ out, int G) {
    int t = blockIdx.x * blockDim.x + threadIdx.x;
    if (t >= G * 32) return;
    int g = t >> 5;
    float inv = 1.f / fmaxf(g_cnt[g], 1.f);
    float4 s = *(const float4*)(g_sums + (size_t)t * 4);
    float4 o = { s.x * inv, s.y * inv, s.z * inv, s.w * inv };
    *(float4*)(out + (size_t)t * 4) = o;
}

// ---------------- launch ----------------
extern "C" void kernel_launch(void* const* d_in, const int* in_sizes, int n_in,
                              void* d_out, int out_size) {
    const float* x     = (const float*)d_in[0];
    const int*   ei    = (const int*)d_in[1];
    const int*   batch = (const int*)d_in[3];
    const float* W1    = (const float*)d_in[4];
    const float* a_s1  = (const float*)d_in[5];
    const float* a_d1  = (const float*)d_in[6];
    const float* b1    = (const float*)d_in[7];
    const float* W2    = (const float*)d_in[8];
    const float* a_s2  = (const float*)d_in[9];
    const float* a_d2  = (const float*)d_in[10];
    const float* b2    = (const float*)d_in[11];
    float*       out   = (float*)d_out;

    int N = in_sizes[0] / 128;
    int E = in_sizes[1] / 2;
    int G = out_size / 128;
    int T = E + N;

    void *pdeg, *ps, *pc;
    cudaGetSymbolAddress(&pdeg, g_deg);
    cudaGetSymbolAddress(&ps, g_sums);
    cudaGetSymbolAddress(&pc, g_cnt);

    // fork a non-blocking side stream for the CSR-independent GEMM work
    cudaStream_t s2;
    cudaStreamCreateWithFlags(&s2, cudaStreamNonBlocking);
    cudaEvent_t eFork, eJoin;
    cudaEventCreateWithFlags(&eFork, cudaEventDisableTiming);
    cudaEventCreateWithFlags(&eJoin, cudaEventDisableTiming);

    cudaEventRecord(eFork, 0);
    cudaStreamWaitEvent(s2, eFork, 0);

    // side stream: fold W2@a2, then GEMM1 (+logits)
    k_wvec<<<1, 256, 0, s2>>>(W2, a_s2, a_d2);
    k_gemm1<<<(N + 63) / 64, 256, 0, s2>>>(x, W1, a_s1, a_d1, N);
    cudaEventRecord(eJoin, s2);

    // main stream: memsets + CSR build
    cudaMemsetAsync(pdeg, 0, (size_t)N * 4);
    cudaMemsetAsync(ps, 0, (size_t)G * 128 * 4);
    cudaMemsetAsync(pc, 0, (size_t)G * 4);

    int nb = (N + 255) / 256;
    k_deg<<<(E + 255) / 256, 256>>>(ei, E);
    k_s1<<<nb, 256>>>(N);
    k_s2<<<1, 512>>>(nb);
    k_s3<<<(N + 256) / 256, 256>>>(N, T);
    k_fill<<<(T + 255) / 256, 256>>>(ei, E, N);

    // join: aggregation needs both CSR and GEMM1 results
    cudaStreamWaitEvent(0, eJoin, 0);

    k_agg1<<<(N + 7) / 8, 256>>>(b1, N);
    k_agg2x<<<(N + 7) / 8, 256>>>(N);
    {
        dim3 grid((N + 63) / 64, 2);
        k_out<<<grid, 256>>>(W2, b2, batch, N);
    }
    k_pool<<<(G * 32 + 255) / 256, 256>>>(out, G);

    // NOTE: stream/event objects are intentionally not destroyed here —
    // destroying capture-referenced objects mid-capture is invalid, and
    // kernel_launch runs only a handful of times (host-side leak only).
}